// round 12
// baseline (speedup 1.0000x reference)
#include <cuda_runtime.h>
#include <cuda_fp16.h>
#include <math.h>
#include <stdint.h>

#define NROWS 8192
#define DDIM  128
#define NT    64          // 8192/128 tiles per side
#define NOFFD 2016        // 64*63/2 strictly-upper pairs
#define NPAIR 2080        // + 64 diagonal
#define THREADS 384       // 8 MMA warps + 4 epilogue warps

// Scratch (__device__ globals: allocation-free rule)
__device__ uint8_t g_h1q[NROWS * DDIM];   // e4m3 of c*normalized h1, c=sqrt(5*log2 e)
__device__ uint8_t g_h2q[NROWS * DDIM];
__device__ float g_R[4 * NROWS];          // [R11 | R12row | R12col | R22]
__device__ float g_diag[NROWS];

// ---------------------------------------------------------------------------
__device__ __forceinline__ uint32_t smem_u32(const void* p) {
    uint32_t a;
    asm("{ .reg .u64 t; cvta.to.shared.u64 t, %1; cvt.u32.u64 %0, t; }"
        : "=r"(a) : "l"(p));
    return a;
}

__device__ __forceinline__ void ldsm_x4(uint32_t& r0, uint32_t& r1,
                                        uint32_t& r2, uint32_t& r3, uint32_t addr) {
    asm volatile("ldmatrix.sync.aligned.m8n8.x4.shared.b16 {%0,%1,%2,%3}, [%4];"
                 : "=r"(r0), "=r"(r1), "=r"(r2), "=r"(r3) : "r"(addr));
}

// fp8 e4m3 MMA with f16 accumulators (2 b32 regs = 4 halves)
__device__ __forceinline__ void mma_fp8_h(uint32_t* d, const uint32_t* a, const uint32_t* b) {
    asm volatile(
        "mma.sync.aligned.m16n8k32.row.col.f16.e4m3.e4m3.f16 "
        "{%0,%1}, {%2,%3,%4,%5}, {%6,%7}, {%0,%1};"
        : "+r"(d[0]), "+r"(d[1])
        : "r"(a[0]), "r"(a[1]), "r"(a[2]), "r"(a[3]), "r"(b[0]), "r"(b[1]));
}

__device__ __forceinline__ uint32_t pack_e4m3x4(float e0, float e1, float e2, float e3) {
    uint32_t r;
    asm("{ .reg .b16 lo, hi;\n\t"
        "cvt.rn.satfinite.e4m3x2.f32 lo, %2, %1;\n\t"
        "cvt.rn.satfinite.e4m3x2.f32 hi, %4, %3;\n\t"
        "mov.b32 %0, {lo, hi}; }"
        : "=r"(r) : "f"(e0), "f"(e1), "f"(e2), "f"(e3));
    return r;
}

// Named barriers: ids 1,2 = full[par], ids 3,4 = empty[par], count = THREADS
__device__ __forceinline__ void bar_sync_n(int id) {
    asm volatile("bar.sync %0, %1;" :: "r"(id), "n"(THREADS) : "memory");
}
__device__ __forceinline__ void bar_arrive_n(int id) {
    asm volatile("bar.arrive %0, %1;" :: "r"(id), "n"(THREADS) : "memory");
}

// ---------------------------------------------------------------------------
// Row-normalize -> e4m3 scaled by C = sqrt(5*log2(e)); exact fp32 diag;
// zero g_R and out.  2 rows per warp (16-lane groups).
// ---------------------------------------------------------------------------
__global__ void norm_kernel(const float* __restrict__ h1,
                            const float* __restrict__ h2,
                            float* __restrict__ out) {
    int gt   = blockIdx.x * blockDim.x + threadIdx.x;
    int lane = gt & 31;
    int row  = (gt >> 5) * 2 + (lane >> 4);
    int gl   = lane & 15;

    if (gt < 4 * NROWS) g_R[gt] = 0.0f;
    if (gt == 0) out[0] = 0.0f;

    const float4* p1 = (const float4*)(h1 + (size_t)row * DDIM);
    const float4* p2 = (const float4*)(h2 + (size_t)row * DDIM);
    float4 a0 = p1[gl * 2], a1 = p1[gl * 2 + 1];
    float4 b0 = p2[gl * 2], b1 = p2[gl * 2 + 1];

    float ss1 = a0.x*a0.x + a0.y*a0.y + a0.z*a0.z + a0.w*a0.w
              + a1.x*a1.x + a1.y*a1.y + a1.z*a1.z + a1.w*a1.w;
    float ss2 = b0.x*b0.x + b0.y*b0.y + b0.z*b0.z + b0.w*b0.w
              + b1.x*b1.x + b1.y*b1.y + b1.z*b1.z + b1.w*b1.w;
    float dt  = a0.x*b0.x + a0.y*b0.y + a0.z*b0.z + a0.w*b0.w
              + a1.x*b1.x + a1.y*b1.y + a1.z*b1.z + a1.w*b1.w;

    #pragma unroll
    for (int m = 8; m > 0; m >>= 1) {
        ss1 += __shfl_xor_sync(0xffffffffu, ss1, m);
        ss2 += __shfl_xor_sync(0xffffffffu, ss2, m);
        dt  += __shfl_xor_sync(0xffffffffu, dt,  m);
    }

    const float C = 2.6857914f;   // sqrt(5*log2(e))
    float in1 = 1.0f / fmaxf(sqrtf(ss1), 1e-12f);
    float in2 = 1.0f / fmaxf(sqrtf(ss2), 1e-12f);
    float s1 = C * in1, s2 = C * in2;

    uint32_t* o1 = (uint32_t*)(g_h1q + (size_t)row * DDIM);
    uint32_t* o2 = (uint32_t*)(g_h2q + (size_t)row * DDIM);
    o1[gl * 2]     = pack_e4m3x4(a0.x*s1, a0.y*s1, a0.z*s1, a0.w*s1);
    o1[gl * 2 + 1] = pack_e4m3x4(a1.x*s1, a1.y*s1, a1.z*s1, a1.w*s1);
    o2[gl * 2]     = pack_e4m3x4(b0.x*s2, b0.y*s2, b0.z*s2, b0.w*s2);
    o2[gl * 2 + 1] = pack_e4m3x4(b1.x*s2, b1.y*s2, b1.z*s2, b1.w*s2);

    if (gl == 0) g_diag[row] = dt * in1 * in2;
}

// ---------------------------------------------------------------------------
// Warp-specialized pair-CTA kernel. 8 MMA warps (wid 0-7) produce f16x2
// accumulator strips into double-buffered SMEM; 4 epilogue warps (wid 8-11)
// consume: exp + row/col reduction + atomics. Ping-pong via named barriers.
// GEMMs per pair (I<=J):
//   g0: h1I*h1J^T  row->R11[I],  col->R11[J] (offd)
//   g1: h2I*h2J^T  row->R22[I],  col->R22[J] (offd)
//   g2: h1I*h2J^T  row->R12r[I], col->R12c[J]
//   g3: h2I*h1J^T  row->R12c[I], col->R12r[J] (offd only)
// Pair order: strictly-upper pairs first, diagonal (3-GEMM) pairs last.
// ---------------------------------------------------------------------------
#define SM_TILE 16384
#define SM_DBUF (4 * SM_TILE)                 // 65536
#define SM_TOTAL (SM_DBUF + 8 * 2048)         // + 8 producer warps x 2 bufs x 1KB

__global__ void __launch_bounds__(THREADS, 2) mma_exp_kernel() {
    extern __shared__ char smem[];
    const uint32_t sb = smem_u32(smem);

    int tid  = threadIdx.x;
    int wid  = tid >> 5;
    int lane = tid & 31;

    // Decode pair index: off-diagonal first, diagonal last
    int p = blockIdx.x, I, J;
    if (p < NOFFD) {
        I = 0;
        while (p >= NT - 1 - I) { p -= NT - 1 - I; I++; }
        J = I + 1 + p;
    } else {
        I = J = p - NOFFD;
    }
    bool offd = (J > I);
    int ngemm = offd ? 4 : 3;

    // ---- Cooperative tile load (all 384 threads)
    {
        const uint4* base[4] = {
            (const uint4*)(g_h1q + (size_t)I * 128 * DDIM),
            (const uint4*)(g_h2q + (size_t)I * 128 * DDIM),
            (const uint4*)(g_h1q + (size_t)J * 128 * DDIM),
            (const uint4*)(g_h2q + (size_t)J * 128 * DDIM)
        };
        for (int idx = tid; idx < 4096; idx += THREADS) {
            int tile = idx >> 10;
            int lidx = idx & 1023;
            int r = lidx >> 3, c = lidx & 7;
            uint32_t off = (uint32_t)tile * SM_TILE + (uint32_t)r * 128u
                         + (uint32_t)((c ^ (r & 7)) << 4);
            *(uint4*)(smem + off) = base[tile][lidx];
        }
    }
    __syncthreads();

    if (wid < 8) {
        // ================= PRODUCER (MMA) warps =================
        int wm = wid >> 2;
        int wn = wid & 3;
        int a_r  = wm * 64 + (lane & 15);
        int a_cp = lane >> 4;
        int b_r  = wn * 32 + ((lane >> 4) << 3) + (lane & 7);
        int b_cp = (lane >> 3) & 1;
        uint32_t dbase = sb + SM_DBUF + (uint32_t)wid * 2048u + (uint32_t)lane * 32u;

        int scnt = 0;
        #pragma unroll 1
        for (int g = 0; g < ngemm; g++) {
            uint32_t As = sb + ((g == 1 || g == 3) ? 1u : 0u) * SM_TILE;
            uint32_t Bs = sb + ((g == 1 || g == 2) ? 3u : 2u) * SM_TILE;

            // Preload ALL B fragments for this GEMM (8 LDSM, 32 regs)
            uint32_t b[4][4][2];
            #pragma unroll
            for (int ks = 0; ks < 4; ks++) {
                #pragma unroll
                for (int np = 0; np < 2; np++) {
                    int r = b_r + np * 16;
                    uint32_t addr = Bs + (uint32_t)r * 128u
                                  + (uint32_t)(((ks * 2 + b_cp) ^ (r & 7)) << 4);
                    ldsm_x4(b[ks][np*2][0], b[ks][np*2][1],
                            b[ks][np*2+1][0], b[ks][np*2+1][1], addr);
                }
            }

            #pragma unroll
            for (int mt = 0; mt < 4; mt++) {
                int par = scnt & 1;
                if (scnt >= 2) bar_sync_n(3 + par);   // wait buffer free

                uint32_t a[4][4];
                int r = a_r + mt * 16;
                #pragma unroll
                for (int ks = 0; ks < 4; ks++) {
                    uint32_t addr = As + (uint32_t)r * 128u
                                  + (uint32_t)(((ks * 2 + a_cp) ^ (r & 7)) << 4);
                    ldsm_x4(a[ks][0], a[ks][1], a[ks][2], a[ks][3], addr);
                }

                uint32_t acc[4][2];
                #pragma unroll
                for (int nt = 0; nt < 4; nt++) { acc[nt][0] = 0u; acc[nt][1] = 0u; }

                #pragma unroll
                for (int ks = 0; ks < 4; ks++)
                    #pragma unroll
                    for (int nt = 0; nt < 4; nt++)
                        mma_fp8_h(acc[nt], a[ks], b[ks][nt]);

                uint32_t daddr = dbase + (uint32_t)par * 1024u;
                asm volatile("st.shared.v4.b32 [%0], {%1,%2,%3,%4};"
                             :: "r"(daddr), "r"(acc[0][0]), "r"(acc[0][1]),
                                "r"(acc[1][0]), "r"(acc[1][1]) : "memory");
                asm volatile("st.shared.v4.b32 [%0], {%1,%2,%3,%4};"
                             :: "r"(daddr + 16u), "r"(acc[2][0]), "r"(acc[2][1]),
                                "r"(acc[3][0]), "r"(acc[3][1]) : "memory");
                bar_arrive_n(1 + par);                // signal buffer full
                scnt++;
            }
        }
    } else {
        // ================= CONSUMER (epilogue) warps =================
        int k = wid - 8;                 // serves producers 2k and 2k+1
        int scnt = 0;

        #pragma unroll 1
        for (int g = 0; g < ngemm; g++) {
            float* Rrow; float* Rcol; bool docol;
            if (g == 0)      { Rrow = g_R + I*128;             Rcol = g_R + J*128;             docol = offd; }
            else if (g == 1) { Rrow = g_R + 3*NROWS + I*128;   Rcol = g_R + 3*NROWS + J*128;   docol = offd; }
            else if (g == 2) { Rrow = g_R + NROWS + I*128;     Rcol = g_R + 2*NROWS + J*128;   docol = true; }
            else             { Rrow = g_R + 2*NROWS + I*128;   Rcol = g_R + NROWS + J*128;     docol = true; }

            __half2 cp[2][4];
            #pragma unroll
            for (int j = 0; j < 2; j++)
                #pragma unroll
                for (int nt = 0; nt < 4; nt++) cp[j][nt] = __half2half2(__ushort_as_half(0));

            #pragma unroll
            for (int mt = 0; mt < 4; mt++) {
                int par = scnt & 1;
                bar_sync_n(1 + par);                  // wait buffer full

                #pragma unroll
                for (int j = 0; j < 2; j++) {
                    int pw  = 2 * k + j;
                    int pwm = pw >> 2, pwn = pw & 3;
                    uint32_t daddr = sb + SM_DBUF + (uint32_t)pw * 2048u
                                   + (uint32_t)par * 1024u + (uint32_t)lane * 32u;
                    uint32_t d[8];
                    asm volatile("ld.shared.v4.b32 {%0,%1,%2,%3}, [%4];"
                                 : "=r"(d[0]), "=r"(d[1]), "=r"(d[2]), "=r"(d[3])
                                 : "r"(daddr));
                    asm volatile("ld.shared.v4.b32 {%0,%1,%2,%3}, [%4];"
                                 : "=r"(d[4]), "=r"(d[5]), "=r"(d[6]), "=r"(d[7])
                                 : "r"(daddr + 16u));

                    __half2 rpA = __half2half2(__ushort_as_half(0));
                    __half2 rpB = rpA;
                    #pragma unroll
                    for (int nt = 0; nt < 4; nt++) {
                        __half2 e01 = h2exp2(*(__half2*)&d[2*nt]);
                        __half2 e23 = h2exp2(*(__half2*)&d[2*nt+1]);
                        rpA = __hadd2(rpA, e01);
                        rpB = __hadd2(rpB, e23);
                        if (docol) cp[j][nt] = __hadd2(cp[j][nt], __hadd2(e01, e23));
                    }
                    rpA = __hadd2(rpA, __shfl_xor_sync(0xffffffffu, rpA, 1));
                    rpA = __hadd2(rpA, __shfl_xor_sync(0xffffffffu, rpA, 2));
                    rpB = __hadd2(rpB, __shfl_xor_sync(0xffffffffu, rpB, 1));
                    rpB = __hadd2(rpB, __shfl_xor_sync(0xffffffffu, rpB, 2));
                    if ((lane & 3) == 0) {
                        int r0 = pwm * 64 + mt * 16 + (lane >> 2);
                        atomicAdd(&Rrow[r0],     __low2float(rpA) + __high2float(rpA));
                        atomicAdd(&Rrow[r0 + 8], __low2float(rpB) + __high2float(rpB));
                    }
                }
                bar_arrive_n(3 + par);                // release buffer
                scnt++;
            }

            if (docol) {
                #pragma unroll
                for (int j = 0; j < 2; j++) {
                    int pwn = (2 * k + j) & 3;
                    #pragma unroll
                    for (int nt = 0; nt < 4; nt++) {
                        __half2 v = cp[j][nt];
                        v = __hadd2(v, __shfl_xor_sync(0xffffffffu, v, 4));
                        v = __hadd2(v, __shfl_xor_sync(0xffffffffu, v, 8));
                        v = __hadd2(v, __shfl_xor_sync(0xffffffffu, v, 16));
                        if (lane < 4) {
                            int c0 = pwn * 32 + lane * 2 + nt * 8;
                            atomicAdd(&Rcol[c0],     __low2float(v));
                            atomicAdd(&Rcol[c0 + 1], __high2float(v));
                        }
                    }
                }
            }
        }
    }
}

// ---------------------------------------------------------------------------
// Final scalar: 32 blocks x 256 threads, one row per thread.
// ---------------------------------------------------------------------------
__global__ void final_kernel(float* out) {
    __shared__ float sm[256];
    int t = threadIdx.x;
    int i = blockIdx.x * 256 + t;
    const float E5 = 148.4131591f;   // exp(1/tau), tau = 0.2

    float n1 = g_R[i]             + g_R[NROWS + i]     - E5;
    float n2 = g_R[3 * NROWS + i] + g_R[2 * NROWS + i] - E5;
    float s  = 0.5f * (__logf(n1) + __logf(n2)) - 5.0f * g_diag[i];

    sm[t] = s;
    __syncthreads();
    #pragma unroll
    for (int o = 128; o > 0; o >>= 1) {
        if (t < o) sm[t] += sm[t + o];
        __syncthreads();
    }
    if (t == 0) atomicAdd(out, sm[0] * (1.0f / NROWS));
}

// ---------------------------------------------------------------------------
extern "C" void kernel_launch(void* const* d_in, const int* in_sizes, int n_in,
                              void* d_out, int out_size) {
    const float* h1 = (const float*)d_in[0];
    const float* h2 = (const float*)d_in[1];
    float* out = (float*)d_out;

    cudaFuncSetAttribute(mma_exp_kernel,
                         cudaFuncAttributeMaxDynamicSharedMemorySize, SM_TOTAL);

    norm_kernel<<<NROWS / 16, 256>>>(h1, h2, out);
    mma_exp_kernel<<<NPAIR, THREADS, SM_TOTAL>>>();
    final_kernel<<<NROWS / 256, 256>>>(out);
}

// round 13
// speedup vs baseline: 1.1907x; 1.1907x over previous
#include <cuda_runtime.h>
#include <cuda_fp16.h>
#include <math.h>
#include <stdint.h>

#define NROWS 8192
#define DDIM  128
#define NT    64          // 8192/128 tiles per side
#define NOFFD 2016        // 64*63/2 strictly-upper pairs
#define NPAIR 2080        // + 64 diagonal

// Scratch (__device__ globals: allocation-free rule)
__device__ uint8_t g_h1q[NROWS * DDIM];   // e4m3 of c*normalized h1, c=sqrt(5*log2 e)
__device__ uint8_t g_h2q[NROWS * DDIM];
__device__ float g_R[4 * NROWS];          // [R11 | R12row | R12col | R22]
__device__ float g_diag[NROWS];

// ---------------------------------------------------------------------------
__device__ __forceinline__ uint32_t smem_u32(const void* p) {
    uint32_t a;
    asm("{ .reg .u64 t; cvta.to.shared.u64 t, %1; cvt.u32.u64 %0, t; }"
        : "=r"(a) : "l"(p));
    return a;
}

__device__ __forceinline__ void ldsm_x4(uint32_t& r0, uint32_t& r1,
                                        uint32_t& r2, uint32_t& r3, uint32_t addr) {
    asm volatile("ldmatrix.sync.aligned.m8n8.x4.shared.b16 {%0,%1,%2,%3}, [%4];"
                 : "=r"(r0), "=r"(r1), "=r"(r2), "=r"(r3) : "r"(addr));
}

// fp8 e4m3 MMA with f16 accumulators (2 b32 regs = 4 halves)
__device__ __forceinline__ void mma_fp8_h(uint32_t* d, const uint32_t* a, const uint32_t* b) {
    asm volatile(
        "mma.sync.aligned.m16n8k32.row.col.f16.e4m3.e4m3.f16 "
        "{%0,%1}, {%2,%3,%4,%5}, {%6,%7}, {%0,%1};"
        : "+r"(d[0]), "+r"(d[1])
        : "r"(a[0]), "r"(a[1]), "r"(a[2]), "r"(a[3]), "r"(b[0]), "r"(b[1]));
}

__device__ __forceinline__ uint32_t pack_e4m3x4(float e0, float e1, float e2, float e3) {
    uint32_t r;
    asm("{ .reg .b16 lo, hi;\n\t"
        "cvt.rn.satfinite.e4m3x2.f32 lo, %2, %1;\n\t"
        "cvt.rn.satfinite.e4m3x2.f32 hi, %4, %3;\n\t"
        "mov.b32 %0, {lo, hi}; }"
        : "=r"(r) : "f"(e0), "f"(e1), "f"(e2), "f"(e3));
    return r;
}

// ---------------------------------------------------------------------------
// Row-normalize -> e4m3 scaled by C = sqrt(5*log2(e)); exact fp32 diag;
// zero g_R and out.  2 rows per warp (16-lane groups).
// ---------------------------------------------------------------------------
__global__ void norm_kernel(const float* __restrict__ h1,
                            const float* __restrict__ h2,
                            float* __restrict__ out) {
    int gt   = blockIdx.x * blockDim.x + threadIdx.x;
    int lane = gt & 31;
    int row  = (gt >> 5) * 2 + (lane >> 4);
    int gl   = lane & 15;

    if (gt < 4 * NROWS) g_R[gt] = 0.0f;
    if (gt == 0) out[0] = 0.0f;

    const float4* p1 = (const float4*)(h1 + (size_t)row * DDIM);
    const float4* p2 = (const float4*)(h2 + (size_t)row * DDIM);
    float4 a0 = p1[gl * 2], a1 = p1[gl * 2 + 1];
    float4 b0 = p2[gl * 2], b1 = p2[gl * 2 + 1];

    float ss1 = a0.x*a0.x + a0.y*a0.y + a0.z*a0.z + a0.w*a0.w
              + a1.x*a1.x + a1.y*a1.y + a1.z*a1.z + a1.w*a1.w;
    float ss2 = b0.x*b0.x + b0.y*b0.y + b0.z*b0.z + b0.w*b0.w
              + b1.x*b1.x + b1.y*b1.y + b1.z*b1.z + b1.w*b1.w;
    float dt  = a0.x*b0.x + a0.y*b0.y + a0.z*b0.z + a0.w*b0.w
              + a1.x*b1.x + a1.y*b1.y + a1.z*b1.z + a1.w*b1.w;

    #pragma unroll
    for (int m = 8; m > 0; m >>= 1) {
        ss1 += __shfl_xor_sync(0xffffffffu, ss1, m);
        ss2 += __shfl_xor_sync(0xffffffffu, ss2, m);
        dt  += __shfl_xor_sync(0xffffffffu, dt,  m);
    }

    const float C = 2.6857914f;   // sqrt(5*log2(e))
    float in1 = 1.0f / fmaxf(sqrtf(ss1), 1e-12f);
    float in2 = 1.0f / fmaxf(sqrtf(ss2), 1e-12f);
    float s1 = C * in1, s2 = C * in2;

    uint32_t* o1 = (uint32_t*)(g_h1q + (size_t)row * DDIM);
    uint32_t* o2 = (uint32_t*)(g_h2q + (size_t)row * DDIM);
    o1[gl * 2]     = pack_e4m3x4(a0.x*s1, a0.y*s1, a0.z*s1, a0.w*s1);
    o1[gl * 2 + 1] = pack_e4m3x4(a1.x*s1, a1.y*s1, a1.z*s1, a1.w*s1);
    o2[gl * 2]     = pack_e4m3x4(b0.x*s2, b0.y*s2, b0.z*s2, b0.w*s2);
    o2[gl * 2 + 1] = pack_e4m3x4(b1.x*s2, b1.y*s2, b1.z*s2, b1.w*s2);

    if (gl == 0) g_diag[row] = dt * in1 * in2;
}

// ---------------------------------------------------------------------------
// Pair-CTA kernel, fp8 MMA + f16 acc, occ 3, lagged strip epilogue.
// One CTA per pair (I<=J), diagonal pairs scheduled last:
//   g0: h1I*h1J^T  row->R11[I],  col->R11[J] (offd)
//   g1: h2I*h2J^T  row->R22[I],  col->R22[J] (offd)
//   g2: h1I*h2J^T  row->R12r[I], col->R12c[J]
//   g3: h2I*h1J^T  row->R12c[I], col->R12r[J] (offd only)
// Strips (16 rows) use double-buffered f16x2 accumulators; the epilogue of
// strip i issues under the MMA shadow of strip i+1 (no register WAR).
// acc (f16) = 5*log2(e)*s, so e = h2exp2(acc) directly.
// ---------------------------------------------------------------------------
#define SM_TILE 16384
#define SM_TOTAL (4 * SM_TILE)

__global__ void __launch_bounds__(256, 3) mma_exp_kernel() {
    extern __shared__ char smem[];
    const uint32_t sb = smem_u32(smem);

    int tid  = threadIdx.x;
    int wid  = tid >> 5;
    int lane = tid & 31;

    // Decode pair index: off-diagonal first, diagonal last
    int p = blockIdx.x, I, J;
    if (p < NOFFD) {
        I = 0;
        while (p >= NT - 1 - I) { p -= NT - 1 - I; I++; }
        J = I + 1 + p;
    } else {
        I = J = p - NOFFD;
    }
    bool offd = (J > I);
    int ngemm = offd ? 4 : 3;

    // ---- Load 4 tiles (h1[I], h2[I], h1[J], h2[J]) into swizzled SMEM
    {
        const uint4* base[4] = {
            (const uint4*)(g_h1q + (size_t)I * 128 * DDIM),
            (const uint4*)(g_h2q + (size_t)I * 128 * DDIM),
            (const uint4*)(g_h1q + (size_t)J * 128 * DDIM),
            (const uint4*)(g_h2q + (size_t)J * 128 * DDIM)
        };
        #pragma unroll
        for (int it = 0; it < 16; it++) {
            int tile = it >> 2;
            int lidx = tid + (it & 3) * 256;
            int r = lidx >> 3, c = lidx & 7;
            uint32_t off = (uint32_t)tile * SM_TILE + (uint32_t)r * 128u
                         + (uint32_t)((c ^ (r & 7)) << 4);
            *(uint4*)(smem + off) = base[tile][lidx];
        }
    }
    __syncthreads();

    int wm = wid >> 2;          // 0..1  (M)
    int wn = wid & 3;           // 0..3  (N)
    int a_r  = wm * 64 + (lane & 15);
    int a_cp = lane >> 4;
    int b_r  = wn * 32 + ((lane >> 4) << 3) + (lane & 7);
    int b_cp = (lane >> 3) & 1;

    #pragma unroll 1
    for (int g = 0; g < ngemm; g++) {
        uint32_t As = sb + ((g == 1 || g == 3) ? 1u : 0u) * SM_TILE;
        uint32_t Bs = sb + ((g == 1 || g == 2) ? 3u : 2u) * SM_TILE;

        float* Rrow; float* Rcol; bool docol;
        if (g == 0)      { Rrow = g_R + I*128;             Rcol = g_R + J*128;             docol = offd; }
        else if (g == 1) { Rrow = g_R + 3*NROWS + I*128;   Rcol = g_R + 3*NROWS + J*128;   docol = offd; }
        else if (g == 2) { Rrow = g_R + NROWS + I*128;     Rcol = g_R + 2*NROWS + J*128;   docol = true; }
        else             { Rrow = g_R + 2*NROWS + I*128;   Rcol = g_R + NROWS + J*128;     docol = true; }

        // ---- Preload ALL B fragments for this GEMM (8 LDSM, 32 regs)
        uint32_t b[4][4][2];   // [kstep][ntile][half]
        #pragma unroll
        for (int ks = 0; ks < 4; ks++) {
            #pragma unroll
            for (int np = 0; np < 2; np++) {
                int r = b_r + np * 16;
                uint32_t addr = Bs + (uint32_t)r * 128u
                              + (uint32_t)(((ks * 2 + b_cp) ^ (r & 7)) << 4);
                ldsm_x4(b[ks][np*2][0], b[ks][np*2][1],
                        b[ks][np*2+1][0], b[ks][np*2+1][1], addr);
            }
        }

        __half2 cp[4];
        #pragma unroll
        for (int nt = 0; nt < 4; nt++) cp[nt] = __half2half2(__ushort_as_half(0));

        // ---- Strips with double-buffered accumulators, epilogue lagged by 1
        uint32_t acc[2][4][2];   // [buf][ntile][half]

        #pragma unroll
        for (int mt = 0; mt < 4; mt++) {
            int buf = mt & 1;
            #pragma unroll
            for (int nt = 0; nt < 4; nt++) { acc[buf][nt][0] = 0u; acc[buf][nt][1] = 0u; }

            int r = a_r + mt * 16;
            #pragma unroll
            for (int ks = 0; ks < 4; ks++) {
                uint32_t a[4];
                uint32_t addr = As + (uint32_t)r * 128u
                              + (uint32_t)(((ks * 2 + a_cp) ^ (r & 7)) << 4);
                ldsm_x4(a[0], a[1], a[2], a[3], addr);
                #pragma unroll
                for (int nt = 0; nt < 4; nt++)
                    mma_fp8_h(acc[buf][nt], a, b[ks][nt]);
            }

            if (mt > 0) {
                // Epilogue of PREVIOUS strip — issues under this strip's MMA shadow
                int pbuf = buf ^ 1;
                __half2 rpA = __half2half2(__ushort_as_half(0));
                __half2 rpB = rpA;
                #pragma unroll
                for (int nt = 0; nt < 4; nt++) {
                    __half2 e01 = h2exp2(*(__half2*)&acc[pbuf][nt][0]);
                    __half2 e23 = h2exp2(*(__half2*)&acc[pbuf][nt][1]);
                    rpA = __hadd2(rpA, e01);
                    rpB = __hadd2(rpB, e23);
                    cp[nt] = __hadd2(cp[nt], __hadd2(e01, e23));
                }
                rpA = __hadd2(rpA, __shfl_xor_sync(0xffffffffu, rpA, 1));
                rpA = __hadd2(rpA, __shfl_xor_sync(0xffffffffu, rpA, 2));
                rpB = __hadd2(rpB, __shfl_xor_sync(0xffffffffu, rpB, 1));
                rpB = __hadd2(rpB, __shfl_xor_sync(0xffffffffu, rpB, 2));
                if ((lane & 3) == 0) {
                    int r0 = wm * 64 + (mt - 1) * 16 + (lane >> 2);
                    atomicAdd(&Rrow[r0],     __low2float(rpA) + __high2float(rpA));
                    atomicAdd(&Rrow[r0 + 8], __low2float(rpB) + __high2float(rpB));
                }
            }
        }
        {   // Final strip's epilogue (mt = 3, buf = 1)
            __half2 rpA = __half2half2(__ushort_as_half(0));
            __half2 rpB = rpA;
            #pragma unroll
            for (int nt = 0; nt < 4; nt++) {
                __half2 e01 = h2exp2(*(__half2*)&acc[1][nt][0]);
                __half2 e23 = h2exp2(*(__half2*)&acc[1][nt][1]);
                rpA = __hadd2(rpA, e01);
                rpB = __hadd2(rpB, e23);
                cp[nt] = __hadd2(cp[nt], __hadd2(e01, e23));
            }
            rpA = __hadd2(rpA, __shfl_xor_sync(0xffffffffu, rpA, 1));
            rpA = __hadd2(rpA, __shfl_xor_sync(0xffffffffu, rpA, 2));
            rpB = __hadd2(rpB, __shfl_xor_sync(0xffffffffu, rpB, 1));
            rpB = __hadd2(rpB, __shfl_xor_sync(0xffffffffu, rpB, 2));
            if ((lane & 3) == 0) {
                int r0 = wm * 64 + 3 * 16 + (lane >> 2);
                atomicAdd(&Rrow[r0],     __low2float(rpA) + __high2float(rpA));
                atomicAdd(&Rrow[r0 + 8], __low2float(rpB) + __high2float(rpB));
            }
        }

        // ---- Column sums for this GEMM
        if (docol) {
            #pragma unroll
            for (int nt = 0; nt < 4; nt++) {
                __half2 v = cp[nt];
                v = __hadd2(v, __shfl_xor_sync(0xffffffffu, v, 4));
                v = __hadd2(v, __shfl_xor_sync(0xffffffffu, v, 8));
                v = __hadd2(v, __shfl_xor_sync(0xffffffffu, v, 16));
                if (lane < 4) {
                    int c0 = wn * 32 + lane * 2 + nt * 8;
                    atomicAdd(&Rcol[c0],     __low2float(v));
                    atomicAdd(&Rcol[c0 + 1], __high2float(v));
                }
            }
        }
    }
}

// ---------------------------------------------------------------------------
// Final scalar: 32 blocks x 256 threads, one row per thread.
// ---------------------------------------------------------------------------
__global__ void final_kernel(float* out) {
    __shared__ float sm[256];
    int t = threadIdx.x;
    int i = blockIdx.x * 256 + t;
    const float E5 = 148.4131591f;   // exp(1/tau), tau = 0.2

    float n1 = g_R[i]             + g_R[NROWS + i]     - E5;
    float n2 = g_R[3 * NROWS + i] + g_R[2 * NROWS + i] - E5;
    float s  = 0.5f * (__logf(n1) + __logf(n2)) - 5.0f * g_diag[i];

    sm[t] = s;
    __syncthreads();
    #pragma unroll
    for (int o = 128; o > 0; o >>= 1) {
        if (t < o) sm[t] += sm[t + o];
        __syncthreads();
    }
    if (t == 0) atomicAdd(out, sm[0] * (1.0f / NROWS));
}

// ---------------------------------------------------------------------------
extern "C" void kernel_launch(void* const* d_in, const int* in_sizes, int n_in,
                              void* d_out, int out_size) {
    const float* h1 = (const float*)d_in[0];
    const float* h2 = (const float*)d_in[1];
    float* out = (float*)d_out;

    cudaFuncSetAttribute(mma_exp_kernel,
                         cudaFuncAttributeMaxDynamicSharedMemorySize, SM_TOTAL);

    norm_kernel<<<NROWS / 16, 256>>>(h1, h2, out);
    mma_exp_kernel<<<NPAIR, 256, SM_TOTAL>>>();
    final_kernel<<<NROWS / 256, 256>>>(out);
}

// round 14
// speedup vs baseline: 1.4064x; 1.1811x over previous
#include <cuda_runtime.h>
#include <cuda_fp16.h>
#include <math.h>
#include <stdint.h>

#define NROWS 8192
#define DDIM  128
#define NT    64          // 8192/128 tiles per side
#define NOFFD 2016        // 64*63/2 strictly-upper pairs
#define NPAIR 2080        // + 64 diagonal

// Scratch (__device__ globals: allocation-free rule)
__device__ uint8_t g_h1q[NROWS * DDIM];   // e4m3 of c*normalized h1, c=sqrt(5*log2 e)
__device__ uint8_t g_h2q[NROWS * DDIM];
__device__ float g_R[4 * NROWS];          // [R11 | R12row | R12col | R22]
__device__ float g_diag[NROWS];

// ---------------------------------------------------------------------------
__device__ __forceinline__ uint32_t smem_u32(const void* p) {
    uint32_t a;
    asm("{ .reg .u64 t; cvta.to.shared.u64 t, %1; cvt.u32.u64 %0, t; }"
        : "=r"(a) : "l"(p));
    return a;
}

__device__ __forceinline__ void ldsm_x4(uint32_t& r0, uint32_t& r1,
                                        uint32_t& r2, uint32_t& r3, uint32_t addr) {
    asm volatile("ldmatrix.sync.aligned.m8n8.x4.shared.b16 {%0,%1,%2,%3}, [%4];"
                 : "=r"(r0), "=r"(r1), "=r"(r2), "=r"(r3) : "r"(addr));
}

// fp8 e4m3 MMA with f16 accumulators (2 b32 regs = 4 halves)
__device__ __forceinline__ void mma_fp8_h(uint32_t* d, const uint32_t* a, const uint32_t* b) {
    asm volatile(
        "mma.sync.aligned.m16n8k32.row.col.f16.e4m3.e4m3.f16 "
        "{%0,%1}, {%2,%3,%4,%5}, {%6,%7}, {%0,%1};"
        : "+r"(d[0]), "+r"(d[1])
        : "r"(a[0]), "r"(a[1]), "r"(a[2]), "r"(a[3]), "r"(b[0]), "r"(b[1]));
}

__device__ __forceinline__ uint32_t pack_e4m3x4(float e0, float e1, float e2, float e3) {
    uint32_t r;
    asm("{ .reg .b16 lo, hi;\n\t"
        "cvt.rn.satfinite.e4m3x2.f32 lo, %2, %1;\n\t"
        "cvt.rn.satfinite.e4m3x2.f32 hi, %4, %3;\n\t"
        "mov.b32 %0, {lo, hi}; }"
        : "=r"(r) : "f"(e0), "f"(e1), "f"(e2), "f"(e3));
    return r;
}

// ---------------------------------------------------------------------------
// Row-normalize -> e4m3 scaled by C = sqrt(5*log2(e)); exact fp32 diag;
// zero g_R and out.  2 rows per warp (16-lane groups).
// ---------------------------------------------------------------------------
__global__ void norm_kernel(const float* __restrict__ h1,
                            const float* __restrict__ h2,
                            float* __restrict__ out) {
    int gt   = blockIdx.x * blockDim.x + threadIdx.x;
    int lane = gt & 31;
    int row  = (gt >> 5) * 2 + (lane >> 4);
    int gl   = lane & 15;

    if (gt < 4 * NROWS) g_R[gt] = 0.0f;
    if (gt == 0) out[0] = 0.0f;

    const float4* p1 = (const float4*)(h1 + (size_t)row * DDIM);
    const float4* p2 = (const float4*)(h2 + (size_t)row * DDIM);
    float4 a0 = p1[gl * 2], a1 = p1[gl * 2 + 1];
    float4 b0 = p2[gl * 2], b1 = p2[gl * 2 + 1];

    float ss1 = a0.x*a0.x + a0.y*a0.y + a0.z*a0.z + a0.w*a0.w
              + a1.x*a1.x + a1.y*a1.y + a1.z*a1.z + a1.w*a1.w;
    float ss2 = b0.x*b0.x + b0.y*b0.y + b0.z*b0.z + b0.w*b0.w
              + b1.x*b1.x + b1.y*b1.y + b1.z*b1.z + b1.w*b1.w;
    float dt  = a0.x*b0.x + a0.y*b0.y + a0.z*b0.z + a0.w*b0.w
              + a1.x*b1.x + a1.y*b1.y + a1.z*b1.z + a1.w*b1.w;

    #pragma unroll
    for (int m = 8; m > 0; m >>= 1) {
        ss1 += __shfl_xor_sync(0xffffffffu, ss1, m);
        ss2 += __shfl_xor_sync(0xffffffffu, ss2, m);
        dt  += __shfl_xor_sync(0xffffffffu, dt,  m);
    }

    const float C = 2.6857914f;   // sqrt(5*log2(e))
    float in1 = 1.0f / fmaxf(sqrtf(ss1), 1e-12f);
    float in2 = 1.0f / fmaxf(sqrtf(ss2), 1e-12f);
    float s1 = C * in1, s2 = C * in2;

    uint32_t* o1 = (uint32_t*)(g_h1q + (size_t)row * DDIM);
    uint32_t* o2 = (uint32_t*)(g_h2q + (size_t)row * DDIM);
    o1[gl * 2]     = pack_e4m3x4(a0.x*s1, a0.y*s1, a0.z*s1, a0.w*s1);
    o1[gl * 2 + 1] = pack_e4m3x4(a1.x*s1, a1.y*s1, a1.z*s1, a1.w*s1);
    o2[gl * 2]     = pack_e4m3x4(b0.x*s2, b0.y*s2, b0.z*s2, b0.w*s2);
    o2[gl * 2 + 1] = pack_e4m3x4(b1.x*s2, b1.y*s2, b1.z*s2, b1.w*s2);

    if (gl == 0) g_diag[row] = dt * in1 * in2;
}

// ---------------------------------------------------------------------------
// Pair-CTA kernel, fp8 MMA + f16 accumulate, occupancy 3.
// One CTA per pair (I<=J), diagonal pairs scheduled last.
// Per-warp GEMM-order rotation: warp w processes GEMMs in order
// (gi + wid) mod ngemm, desynchronizing epilogue phases across warps so
// the tensor pipe stays fed while individual warps run their epilogues.
//   g0: h1I*h1J^T  row->R11[I],  col->R11[J] (offd)
//   g1: h2I*h2J^T  row->R22[I],  col->R22[J] (offd)
//   g2: h1I*h2J^T  row->R12r[I], col->R12c[J]
//   g3: h2I*h1J^T  row->R12c[I], col->R12r[J] (offd only)
// ks-outer mainloop: whole 128x32 warp tile accumulated in 32 f16x2 regs.
// acc (f16) = 5*log2(e)*s, so e = h2exp2(acc) directly.
// ---------------------------------------------------------------------------
#define SM_TILE 16384
#define SM_TOTAL (4 * SM_TILE)

__global__ void __launch_bounds__(256, 3) mma_exp_kernel() {
    extern __shared__ char smem[];
    const uint32_t sb = smem_u32(smem);

    int tid  = threadIdx.x;
    int wid  = tid >> 5;
    int lane = tid & 31;

    // Decode pair index: off-diagonal first, diagonal last
    int p = blockIdx.x, I, J;
    if (p < NOFFD) {
        I = 0;
        while (p >= NT - 1 - I) { p -= NT - 1 - I; I++; }
        J = I + 1 + p;
    } else {
        I = J = p - NOFFD;
    }
    bool offd = (J > I);
    int ngemm = offd ? 4 : 3;

    // ---- Load 4 tiles (h1[I], h2[I], h1[J], h2[J]) into swizzled SMEM
    {
        const uint4* base[4] = {
            (const uint4*)(g_h1q + (size_t)I * 128 * DDIM),
            (const uint4*)(g_h2q + (size_t)I * 128 * DDIM),
            (const uint4*)(g_h1q + (size_t)J * 128 * DDIM),
            (const uint4*)(g_h2q + (size_t)J * 128 * DDIM)
        };
        #pragma unroll
        for (int it = 0; it < 16; it++) {
            int tile = it >> 2;
            int lidx = tid + (it & 3) * 256;
            int r = lidx >> 3, c = lidx & 7;
            uint32_t off = (uint32_t)tile * SM_TILE + (uint32_t)r * 128u
                         + (uint32_t)((c ^ (r & 7)) << 4);
            *(uint4*)(smem + off) = base[tile][lidx];
        }
    }
    __syncthreads();

    int wm = wid >> 2;          // 0..1  (M)
    int wn = wid & 3;           // 0..3  (N)
    int a_r  = wm * 64 + (lane & 15);
    int a_cp = lane >> 4;
    int b_r  = wn * 32 + ((lane >> 4) << 3) + (lane & 7);
    int b_cp = (lane >> 3) & 1;

    int grot = wid % ngemm;     // per-warp starting GEMM

    #pragma unroll 1
    for (int gi = 0; gi < ngemm; gi++) {
        int g = gi + grot;
        if (g >= ngemm) g -= ngemm;

        uint32_t As = sb + ((g == 1 || g == 3) ? 1u : 0u) * SM_TILE;
        uint32_t Bs = sb + ((g == 1 || g == 2) ? 3u : 2u) * SM_TILE;

        float* Rrow; float* Rcol; bool docol;
        if (g == 0)      { Rrow = g_R + I*128;             Rcol = g_R + J*128;             docol = offd; }
        else if (g == 1) { Rrow = g_R + 3*NROWS + I*128;   Rcol = g_R + 3*NROWS + J*128;   docol = offd; }
        else if (g == 2) { Rrow = g_R + NROWS + I*128;     Rcol = g_R + 2*NROWS + J*128;   docol = true; }
        else             { Rrow = g_R + 2*NROWS + I*128;   Rcol = g_R + NROWS + J*128;     docol = true; }

        // ---- ks-outer mainloop: f16x2 accumulators for the whole warp tile
        uint32_t acc[4][4][2];   // [mtile][ntile][half-pair]
        #pragma unroll
        for (int mt = 0; mt < 4; mt++)
            #pragma unroll
            for (int nt = 0; nt < 4; nt++) { acc[mt][nt][0] = 0u; acc[mt][nt][1] = 0u; }

        #pragma unroll
        for (int ks = 0; ks < 4; ks++) {
            int kc = ks * 2;
            uint32_t a[4][4];
            #pragma unroll
            for (int mt = 0; mt < 4; mt++) {
                int r = a_r + mt * 16;
                uint32_t addr = As + (uint32_t)r * 128u
                              + (uint32_t)(((kc + a_cp) ^ (r & 7)) << 4);
                ldsm_x4(a[mt][0], a[mt][1], a[mt][2], a[mt][3], addr);
            }
            uint32_t b[4][2];
            #pragma unroll
            for (int np = 0; np < 2; np++) {
                int r = b_r + np * 16;
                uint32_t addr = Bs + (uint32_t)r * 128u
                              + (uint32_t)(((kc + b_cp) ^ (r & 7)) << 4);
                ldsm_x4(b[np*2][0], b[np*2][1], b[np*2+1][0], b[np*2+1][1], addr);
            }
            #pragma unroll
            for (int mt = 0; mt < 4; mt++)
                #pragma unroll
                for (int nt = 0; nt < 4; nt++)
                    mma_fp8_h(acc[mt][nt], a[mt], b[nt]);
        }

        // ---- Epilogue: e = 2^acc, packed half2 throughout
        __half2 cp[4];
        #pragma unroll
        for (int nt = 0; nt < 4; nt++) cp[nt] = __half2half2(__ushort_as_half(0));

        #pragma unroll
        for (int mt = 0; mt < 4; mt++) {
            __half2 rpA = __half2half2(__ushort_as_half(0));  // (row r: c0,c1)
            __half2 rpB = rpA;                                 // (row r+8: c2,c3)
            #pragma unroll
            for (int nt = 0; nt < 4; nt++) {
                __half2 e01 = h2exp2(*(__half2*)&acc[mt][nt][0]);
                __half2 e23 = h2exp2(*(__half2*)&acc[mt][nt][1]);
                rpA = __hadd2(rpA, e01);
                rpB = __hadd2(rpB, e23);
                cp[nt] = __hadd2(cp[nt], __hadd2(e01, e23));   // (e0+e2, e1+e3)
            }
            rpA = __hadd2(rpA, __shfl_xor_sync(0xffffffffu, rpA, 1));
            rpA = __hadd2(rpA, __shfl_xor_sync(0xffffffffu, rpA, 2));
            rpB = __hadd2(rpB, __shfl_xor_sync(0xffffffffu, rpB, 1));
            rpB = __hadd2(rpB, __shfl_xor_sync(0xffffffffu, rpB, 2));
            if ((lane & 3) == 0) {
                int r0 = wm * 64 + mt * 16 + (lane >> 2);
                atomicAdd(&Rrow[r0],     __low2float(rpA) + __high2float(rpA));
                atomicAdd(&Rrow[r0 + 8], __low2float(rpB) + __high2float(rpB));
            }
        }

        // ---- Column sums for this GEMM
        if (docol) {
            #pragma unroll
            for (int nt = 0; nt < 4; nt++) {
                __half2 v = cp[nt];
                v = __hadd2(v, __shfl_xor_sync(0xffffffffu, v, 4));
                v = __hadd2(v, __shfl_xor_sync(0xffffffffu, v, 8));
                v = __hadd2(v, __shfl_xor_sync(0xffffffffu, v, 16));
                if (lane < 4) {
                    int c0 = wn * 32 + lane * 2 + nt * 8;
                    atomicAdd(&Rcol[c0],     __low2float(v));
                    atomicAdd(&Rcol[c0 + 1], __high2float(v));
                }
            }
        }
    }
}

// ---------------------------------------------------------------------------
// Final scalar: 32 blocks x 256 threads, one row per thread.
// ---------------------------------------------------------------------------
__global__ void final_kernel(float* out) {
    __shared__ float sm[256];
    int t = threadIdx.x;
    int i = blockIdx.x * 256 + t;
    const float E5 = 148.4131591f;   // exp(1/tau), tau = 0.2

    float n1 = g_R[i]             + g_R[NROWS + i]     - E5;
    float n2 = g_R[3 * NROWS + i] + g_R[2 * NROWS + i] - E5;
    float s  = 0.5f * (__logf(n1) + __logf(n2)) - 5.0f * g_diag[i];

    sm[t] = s;
    __syncthreads();
    #pragma unroll
    for (int o = 128; o > 0; o >>= 1) {
        if (t < o) sm[t] += sm[t + o];
        __syncthreads();
    }
    if (t == 0) atomicAdd(out, sm[0] * (1.0f / NROWS));
}

// ---------------------------------------------------------------------------
extern "C" void kernel_launch(void* const* d_in, const int* in_sizes, int n_in,
                              void* d_out, int out_size) {
    const float* h1 = (const float*)d_in[0];
    const float* h2 = (const float*)d_in[1];
    float* out = (float*)d_out;

    cudaFuncSetAttribute(mma_exp_kernel,
                         cudaFuncAttributeMaxDynamicSharedMemorySize, SM_TOTAL);

    norm_kernel<<<NROWS / 16, 256>>>(h1, h2, out);
    mma_exp_kernel<<<NPAIR, 256, SM_TOTAL>>>();
    final_kernel<<<NROWS / 256, 256>>>(out);
}

// round 16
// speedup vs baseline: 1.4608x; 1.0387x over previous
#include <cuda_runtime.h>
#include <cuda_fp16.h>
#include <math.h>
#include <stdint.h>

#define NROWS 8192
#define DDIM  128
#define NT    64          // 8192/128 tiles per side
#define NPAIR 2080        // 64*65/2

// Scratch (__device__ globals: allocation-free rule)
__device__ uint8_t g_h1q[NROWS * DDIM];   // e4m3 of c*normalized h1, c=sqrt(5*log2 e)
__device__ uint8_t g_h2q[NROWS * DDIM];
__device__ float g_R[4 * NROWS];          // [R11 | R12row | R12col | R22]
__device__ float g_diag[NROWS];

// ---------------------------------------------------------------------------
__device__ __forceinline__ uint32_t smem_u32(const void* p) {
    uint32_t a;
    asm("{ .reg .u64 t; cvta.to.shared.u64 t, %1; cvt.u32.u64 %0, t; }"
        : "=r"(a) : "l"(p));
    return a;
}

__device__ __forceinline__ void ldsm_x4(uint32_t& r0, uint32_t& r1,
                                        uint32_t& r2, uint32_t& r3, uint32_t addr) {
    asm volatile("ldmatrix.sync.aligned.m8n8.x4.shared.b16 {%0,%1,%2,%3}, [%4];"
                 : "=r"(r0), "=r"(r1), "=r"(r2), "=r"(r3) : "r"(addr));
}

// fp8 e4m3 MMA with f16 accumulators (2 b32 regs = 4 halves)
__device__ __forceinline__ void mma_fp8_h(uint32_t* d, const uint32_t* a, const uint32_t* b) {
    asm volatile(
        "mma.sync.aligned.m16n8k32.row.col.f16.e4m3.e4m3.f16 "
        "{%0,%1}, {%2,%3,%4,%5}, {%6,%7}, {%0,%1};"
        : "+r"(d[0]), "+r"(d[1])
        : "r"(a[0]), "r"(a[1]), "r"(a[2]), "r"(a[3]), "r"(b[0]), "r"(b[1]));
}

__device__ __forceinline__ uint32_t pack_e4m3x4(float e0, float e1, float e2, float e3) {
    uint32_t r;
    asm("{ .reg .b16 lo, hi;\n\t"
        "cvt.rn.satfinite.e4m3x2.f32 lo, %2, %1;\n\t"
        "cvt.rn.satfinite.e4m3x2.f32 hi, %4, %3;\n\t"
        "mov.b32 %0, {lo, hi}; }"
        : "=r"(r) : "f"(e0), "f"(e1), "f"(e2), "f"(e3));
    return r;
}

// ---------------------------------------------------------------------------
// Row-normalize -> e4m3 scaled by C = sqrt(5*log2(e)); exact fp32 diag;
// zero g_R and out.  2 rows per warp (16-lane groups).
// ---------------------------------------------------------------------------
__global__ void norm_kernel(const float* __restrict__ h1,
                            const float* __restrict__ h2,
                            float* __restrict__ out) {
    int gt   = blockIdx.x * blockDim.x + threadIdx.x;
    int lane = gt & 31;
    int row  = (gt >> 5) * 2 + (lane >> 4);
    int gl   = lane & 15;

    if (gt < 4 * NROWS) g_R[gt] = 0.0f;
    if (gt == 0) out[0] = 0.0f;

    const float4* p1 = (const float4*)(h1 + (size_t)row * DDIM);
    const float4* p2 = (const float4*)(h2 + (size_t)row * DDIM);
    float4 a0 = p1[gl * 2], a1 = p1[gl * 2 + 1];
    float4 b0 = p2[gl * 2], b1 = p2[gl * 2 + 1];

    float ss1 = a0.x*a0.x + a0.y*a0.y + a0.z*a0.z + a0.w*a0.w
              + a1.x*a1.x + a1.y*a1.y + a1.z*a1.z + a1.w*a1.w;
    float ss2 = b0.x*b0.x + b0.y*b0.y + b0.z*b0.z + b0.w*b0.w
              + b1.x*b1.x + b1.y*b1.y + b1.z*b1.z + b1.w*b1.w;
    float dt  = a0.x*b0.x + a0.y*b0.y + a0.z*b0.z + a0.w*b0.w
              + a1.x*b1.x + a1.y*b1.y + a1.z*b1.z + a1.w*b1.w;

    #pragma unroll
    for (int m = 8; m > 0; m >>= 1) {
        ss1 += __shfl_xor_sync(0xffffffffu, ss1, m);
        ss2 += __shfl_xor_sync(0xffffffffu, ss2, m);
        dt  += __shfl_xor_sync(0xffffffffu, dt,  m);
    }

    const float C = 2.6857914f;   // sqrt(5*log2(e))
    float in1 = 1.0f / fmaxf(sqrtf(ss1), 1e-12f);
    float in2 = 1.0f / fmaxf(sqrtf(ss2), 1e-12f);
    float s1 = C * in1, s2 = C * in2;

    uint32_t* o1 = (uint32_t*)(g_h1q + (size_t)row * DDIM);
    uint32_t* o2 = (uint32_t*)(g_h2q + (size_t)row * DDIM);
    o1[gl * 2]     = pack_e4m3x4(a0.x*s1, a0.y*s1, a0.z*s1, a0.w*s1);
    o1[gl * 2 + 1] = pack_e4m3x4(a1.x*s1, a1.y*s1, a1.z*s1, a1.w*s1);
    o2[gl * 2]     = pack_e4m3x4(b0.x*s2, b0.y*s2, b0.z*s2, b0.w*s2);
    o2[gl * 2 + 1] = pack_e4m3x4(b1.x*s2, b1.y*s2, b1.z*s2, b1.w*s2);

    if (gl == 0) g_diag[row] = dt * in1 * in2;
}

// ---------------------------------------------------------------------------
// Pair-CTA kernel, fp8 MMA + f16 accumulate, occupancy 3.
// SMEM tiles stored CHUNK-MAJOR: offset(c, r) = c*2064 + r*16  (c = 16B
// k-chunk 0..7, r = row 0..127; 2064 = 2048+16 pad kills ST conflicts).
// All LDSM addresses in the mainloop are laneBase + compile-time constants
// (ks*4128 + mt*256) — no XOR swizzle math in the hot loop.
// One CTA per pair (I<=J):
//   g0: h1I*h1J^T  row->R11[I],  col->R11[J] (offd)
//   g1: h2I*h2J^T  row->R22[I],  col->R22[J] (offd)
//   g2: h1I*h2J^T  row->R12r[I], col->R12c[J]
//   g3: h2I*h1J^T  row->R12c[I], col->R12r[J] (offd only)
// ks-outer mainloop, whole 128x32 warp tile in 32 f16x2 accumulator regs.
// acc (f16) = 5*log2(e)*s, so e = h2exp2(acc) directly.
// ---------------------------------------------------------------------------
#define CH_STRIDE 2064
#define SM_TILE   (8 * CH_STRIDE)      // 16512
#define SM_TOTAL  (4 * SM_TILE)        // 66048

__global__ void __launch_bounds__(256, 3) mma_exp_kernel() {
    extern __shared__ char smem[];
    const uint32_t sb = smem_u32(smem);

    int tid  = threadIdx.x;
    int wid  = tid >> 5;
    int lane = tid & 31;

    // Decode triangular pair index -> (I, J), I<=J
    int p = blockIdx.x, I = 0;
    while (p >= NT - I) { p -= NT - I; I++; }
    int J = I + p;
    bool offd = (J > I);
    int ngemm = offd ? 4 : 3;

    // ---- Load 4 tiles (h1[I], h2[I], h1[J], h2[J]) into chunk-major SMEM
    {
        const uint4* base[4] = {
            (const uint4*)(g_h1q + (size_t)I * 128 * DDIM),
            (const uint4*)(g_h2q + (size_t)I * 128 * DDIM),
            (const uint4*)(g_h1q + (size_t)J * 128 * DDIM),
            (const uint4*)(g_h2q + (size_t)J * 128 * DDIM)
        };
        #pragma unroll
        for (int it = 0; it < 16; it++) {
            int tile = it >> 2;
            int lidx = tid + (it & 3) * 256;   // chunk index within tile (r*8+c)
            int r = lidx >> 3, c = lidx & 7;
            uint32_t off = (uint32_t)tile * SM_TILE
                         + (uint32_t)c * CH_STRIDE + (uint32_t)r * 16u;
            *(uint4*)(smem + off) = base[tile][lidx];
        }
    }
    __syncthreads();

    int wm = wid >> 2;          // 0..1  (M)
    int wn = wid & 3;           // 0..3  (N)
    int a_r  = wm * 64 + (lane & 15);
    int a_cp = lane >> 4;
    int b_r  = wn * 32 + ((lane >> 4) << 3) + (lane & 7);
    int b_cp = (lane >> 3) & 1;

    // Per-lane invariant parts of the LDSM addresses (chunk-major layout)
    uint32_t aLane = (uint32_t)a_cp * CH_STRIDE + (uint32_t)a_r * 16u;
    uint32_t bLane = (uint32_t)b_cp * CH_STRIDE + (uint32_t)b_r * 16u;

    #pragma unroll 1
    for (int g = 0; g < ngemm; g++) {
        uint32_t As = sb + ((g == 1 || g == 3) ? 1u : 0u) * SM_TILE;
        uint32_t Bs = sb + ((g == 1 || g == 2) ? 3u : 2u) * SM_TILE;

        float* Rrow; float* Rcol; bool docol;
        if (g == 0)      { Rrow = g_R + I*128;             Rcol = g_R + J*128;             docol = offd; }
        else if (g == 1) { Rrow = g_R + 3*NROWS + I*128;   Rcol = g_R + 3*NROWS + J*128;   docol = offd; }
        else if (g == 2) { Rrow = g_R + NROWS + I*128;     Rcol = g_R + 2*NROWS + J*128;   docol = true; }
        else             { Rrow = g_R + 2*NROWS + I*128;   Rcol = g_R + NROWS + J*128;     docol = true; }

        uint32_t aBase = As + aLane;
        uint32_t bBase = Bs + bLane;

        // ---- ks-outer mainloop: f16x2 accumulators for the whole warp tile
        uint32_t acc[4][4][2];   // [mtile][ntile][half-pair]
        #pragma unroll
        for (int mt = 0; mt < 4; mt++)
            #pragma unroll
            for (int nt = 0; nt < 4; nt++) { acc[mt][nt][0] = 0u; acc[mt][nt][1] = 0u; }

        #pragma unroll
        for (int ks = 0; ks < 4; ks++) {
            uint32_t kofs = (uint32_t)ks * (2u * CH_STRIDE);   // 2 chunks per kstep
            uint32_t a[4][4];
            #pragma unroll
            for (int mt = 0; mt < 4; mt++)
                ldsm_x4(a[mt][0], a[mt][1], a[mt][2], a[mt][3],
                        aBase + kofs + (uint32_t)(mt * 256));
            uint32_t b[4][2];
            #pragma unroll
            for (int np = 0; np < 2; np++)
                ldsm_x4(b[np*2][0], b[np*2][1], b[np*2+1][0], b[np*2+1][1],
                        bBase + kofs + (uint32_t)(np * 256));
            #pragma unroll
            for (int mt = 0; mt < 4; mt++)
                #pragma unroll
                for (int nt = 0; nt < 4; nt++)
                    mma_fp8_h(acc[mt][nt], a[mt], b[nt]);
        }

        // ---- Epilogue: e = 2^acc, packed half2 throughout
        __half2 cp[4];
        #pragma unroll
        for (int nt = 0; nt < 4; nt++) cp[nt] = __half2half2(__ushort_as_half(0));

        #pragma unroll
        for (int mt = 0; mt < 4; mt++) {
            __half2 rpA = __half2half2(__ushort_as_half(0));  // (row r: c0,c1)
            __half2 rpB = rpA;                                 // (row r+8: c2,c3)
            #pragma unroll
            for (int nt = 0; nt < 4; nt++) {
                __half2 e01 = h2exp2(*(__half2*)&acc[mt][nt][0]);
                __half2 e23 = h2exp2(*(__half2*)&acc[mt][nt][1]);
                rpA = __hadd2(rpA, e01);
                rpB = __hadd2(rpB, e23);
                cp[nt] = __hadd2(cp[nt], __hadd2(e01, e23));   // (e0+e2, e1+e3)
            }
            rpA = __hadd2(rpA, __shfl_xor_sync(0xffffffffu, rpA, 1));
            rpA = __hadd2(rpA, __shfl_xor_sync(0xffffffffu, rpA, 2));
            rpB = __hadd2(rpB, __shfl_xor_sync(0xffffffffu, rpB, 1));
            rpB = __hadd2(rpB, __shfl_xor_sync(0xffffffffu, rpB, 2));
            if ((lane & 3) == 0) {
                int r0 = wm * 64 + mt * 16 + (lane >> 2);
                atomicAdd(&Rrow[r0],     __low2float(rpA) + __high2float(rpA));
                atomicAdd(&Rrow[r0 + 8], __low2float(rpB) + __high2float(rpB));
            }
        }

        // ---- Column sums for this GEMM
        if (docol) {
            #pragma unroll
            for (int nt = 0; nt < 4; nt++) {
                __half2 v = cp[nt];
                v = __hadd2(v, __shfl_xor_sync(0xffffffffu, v, 4));
                v = __hadd2(v, __shfl_xor_sync(0xffffffffu, v, 8));
                v = __hadd2(v, __shfl_xor_sync(0xffffffffu, v, 16));
                if (lane < 4) {
                    int c0 = wn * 32 + lane * 2 + nt * 8;
                    atomicAdd(&Rcol[c0],     __low2float(v));
                    atomicAdd(&Rcol[c0 + 1], __high2float(v));
                }
            }
        }
    }
}

// ---------------------------------------------------------------------------
// Final scalar: 32 blocks x 256 threads, one row per thread.
// ---------------------------------------------------------------------------
__global__ void final_kernel(float* out) {
    __shared__ float sm[256];
    int t = threadIdx.x;
    int i = blockIdx.x * 256 + t;
    const float E5 = 148.4131591f;   // exp(1/tau), tau = 0.2

    float n1 = g_R[i]             + g_R[NROWS + i]     - E5;
    float n2 = g_R[3 * NROWS + i] + g_R[2 * NROWS + i] - E5;
    float s  = 0.5f * (__logf(n1) + __logf(n2)) - 5.0f * g_diag[i];

    sm[t] = s;
    __syncthreads();
    #pragma unroll
    for (int o = 128; o > 0; o >>= 1) {
        if (t < o) sm[t] += sm[t + o];
        __syncthreads();
    }
    if (t == 0) atomicAdd(out, sm[0] * (1.0f / NROWS));
}

// ---------------------------------------------------------------------------
extern "C" void kernel_launch(void* const* d_in, const int* in_sizes, int n_in,
                              void* d_out, int out_size) {
    const float* h1 = (const float*)d_in[0];
    const float* h2 = (const float*)d_in[1];
    float* out = (float*)d_out;

    cudaFuncSetAttribute(mma_exp_kernel,
                         cudaFuncAttributeMaxDynamicSharedMemorySize, SM_TOTAL);

    norm_kernel<<<NROWS / 16, 256>>>(h1, h2, out);
    mma_exp_kernel<<<NPAIR, 256, SM_TOTAL>>>();
    final_kernel<<<NROWS / 256, 256>>>(out);
}

// round 17
// speedup vs baseline: 1.4821x; 1.0146x over previous
#include <cuda_runtime.h>
#include <cuda_fp16.h>
#include <math.h>
#include <stdint.h>

#define NROWS 8192
#define DDIM  128
#define NT    64          // 8192/128 tiles per side
#define NOFFD 2016        // 64*63/2 strictly-upper pairs
#define NPAIR 2080        // + 64 diagonal

// Scratch (__device__ globals: allocation-free rule)
__device__ uint8_t g_h1q[NROWS * DDIM];   // e4m3 of c*normalized h1, c=sqrt(5*log2 e)
__device__ uint8_t g_h2q[NROWS * DDIM];
__device__ float g_R[4 * NROWS];          // [R11 | R12row | R12col | R22]
__device__ float g_diag[NROWS];

// ---------------------------------------------------------------------------
__device__ __forceinline__ uint32_t smem_u32(const void* p) {
    uint32_t a;
    asm("{ .reg .u64 t; cvta.to.shared.u64 t, %1; cvt.u32.u64 %0, t; }"
        : "=r"(a) : "l"(p));
    return a;
}

__device__ __forceinline__ void ldsm_x4(uint32_t& r0, uint32_t& r1,
                                        uint32_t& r2, uint32_t& r3, uint32_t addr) {
    asm volatile("ldmatrix.sync.aligned.m8n8.x4.shared.b16 {%0,%1,%2,%3}, [%4];"
                 : "=r"(r0), "=r"(r1), "=r"(r2), "=r"(r3) : "r"(addr));
}

// fp8 e4m3 MMA with f16 accumulators (2 b32 regs = 4 halves)
__device__ __forceinline__ void mma_fp8_h(uint32_t* d, const uint32_t* a, const uint32_t* b) {
    asm volatile(
        "mma.sync.aligned.m16n8k32.row.col.f16.e4m3.e4m3.f16 "
        "{%0,%1}, {%2,%3,%4,%5}, {%6,%7}, {%0,%1};"
        : "+r"(d[0]), "+r"(d[1])
        : "r"(a[0]), "r"(a[1]), "r"(a[2]), "r"(a[3]), "r"(b[0]), "r"(b[1]));
}

__device__ __forceinline__ uint32_t pack_e4m3x4(float e0, float e1, float e2, float e3) {
    uint32_t r;
    asm("{ .reg .b16 lo, hi;\n\t"
        "cvt.rn.satfinite.e4m3x2.f32 lo, %2, %1;\n\t"
        "cvt.rn.satfinite.e4m3x2.f32 hi, %4, %3;\n\t"
        "mov.b32 %0, {lo, hi}; }"
        : "=r"(r) : "f"(e0), "f"(e1), "f"(e2), "f"(e3));
    return r;
}

// Programmatic dependent launch controls (base sm_90 PTX, family-safe)
#define GRIDDEP_WAIT()   asm volatile("griddepcontrol.wait;" ::: "memory")
#define GRIDDEP_LAUNCH() asm volatile("griddepcontrol.launch_dependents;" ::: "memory")

// ---------------------------------------------------------------------------
// Row-normalize -> e4m3 scaled by C = sqrt(5*log2(e)); exact fp32 diag;
// zero g_R and out.  2 rows per warp (16-lane groups).
// ---------------------------------------------------------------------------
__global__ void norm_kernel(const float* __restrict__ h1,
                            const float* __restrict__ h2,
                            float* __restrict__ out) {
    int gt   = blockIdx.x * blockDim.x + threadIdx.x;
    int lane = gt & 31;
    int row  = (gt >> 5) * 2 + (lane >> 4);
    int gl   = lane & 15;

    if (gt < 4 * NROWS) g_R[gt] = 0.0f;
    if (gt == 0) out[0] = 0.0f;

    const float4* p1 = (const float4*)(h1 + (size_t)row * DDIM);
    const float4* p2 = (const float4*)(h2 + (size_t)row * DDIM);
    float4 a0 = p1[gl * 2], a1 = p1[gl * 2 + 1];
    float4 b0 = p2[gl * 2], b1 = p2[gl * 2 + 1];

    float ss1 = a0.x*a0.x + a0.y*a0.y + a0.z*a0.z + a0.w*a0.w
              + a1.x*a1.x + a1.y*a1.y + a1.z*a1.z + a1.w*a1.w;
    float ss2 = b0.x*b0.x + b0.y*b0.y + b0.z*b0.z + b0.w*b0.w
              + b1.x*b1.x + b1.y*b1.y + b1.z*b1.z + b1.w*b1.w;
    float dt  = a0.x*b0.x + a0.y*b0.y + a0.z*b0.z + a0.w*b0.w
              + a1.x*b1.x + a1.y*b1.y + a1.z*b1.z + a1.w*b1.w;

    #pragma unroll
    for (int m = 8; m > 0; m >>= 1) {
        ss1 += __shfl_xor_sync(0xffffffffu, ss1, m);
        ss2 += __shfl_xor_sync(0xffffffffu, ss2, m);
        dt  += __shfl_xor_sync(0xffffffffu, dt,  m);
    }

    const float C = 2.6857914f;   // sqrt(5*log2(e))
    float in1 = 1.0f / fmaxf(sqrtf(ss1), 1e-12f);
    float in2 = 1.0f / fmaxf(sqrtf(ss2), 1e-12f);
    float s1 = C * in1, s2 = C * in2;

    uint32_t* o1 = (uint32_t*)(g_h1q + (size_t)row * DDIM);
    uint32_t* o2 = (uint32_t*)(g_h2q + (size_t)row * DDIM);
    o1[gl * 2]     = pack_e4m3x4(a0.x*s1, a0.y*s1, a0.z*s1, a0.w*s1);
    o1[gl * 2 + 1] = pack_e4m3x4(a1.x*s1, a1.y*s1, a1.z*s1, a1.w*s1);
    o2[gl * 2]     = pack_e4m3x4(b0.x*s2, b0.y*s2, b0.z*s2, b0.w*s2);
    o2[gl * 2 + 1] = pack_e4m3x4(b1.x*s2, b1.y*s2, b1.z*s2, b1.w*s2);

    if (gl == 0) g_diag[row] = dt * in1 * in2;

    GRIDDEP_LAUNCH();   // all writes above are visible to dependents
}

// ---------------------------------------------------------------------------
// Pair-CTA kernel, fp8 MMA + f16 accumulate, occupancy 3.
// SMEM tiles stored CHUNK-MAJOR: offset(c, r) = c*2064 + r*16 (16B k-chunk c,
// row r; pad 2064 kills store conflicts). LDSM addresses in the mainloop are
// laneBase + compile-time constants — no swizzle math in the hot loop.
// One CTA per pair (I<=J), diagonal (3-GEMM) pairs scheduled LAST:
//   g0: h1I*h1J^T  row->R11[I],  col->R11[J] (offd)
//   g1: h2I*h2J^T  row->R22[I],  col->R22[J] (offd)
//   g2: h1I*h2J^T  row->R12r[I], col->R12c[J]
//   g3: h2I*h1J^T  row->R12c[I], col->R12r[J] (offd only)
// ks-outer mainloop, whole 128x32 warp tile in 32 f16x2 accumulator regs.
// acc (f16) = 5*log2(e)*s, so e = h2exp2(acc) directly.
// ---------------------------------------------------------------------------
#define CH_STRIDE 2064
#define SM_TILE   (8 * CH_STRIDE)      // 16512
#define SM_TOTAL  (4 * SM_TILE)        // 66048

__global__ void __launch_bounds__(256, 3) mma_exp_kernel() {
    extern __shared__ char smem[];
    const uint32_t sb = smem_u32(smem);

    int tid  = threadIdx.x;
    int wid  = tid >> 5;
    int lane = tid & 31;

    // Decode pair index: off-diagonal first, diagonal last
    int p = blockIdx.x, I, J;
    if (p < NOFFD) {
        I = 0;
        while (p >= NT - 1 - I) { p -= NT - 1 - I; I++; }
        J = I + 1 + p;
    } else {
        I = J = p - NOFFD;
    }
    bool offd = (J > I);
    int ngemm = offd ? 4 : 3;

    GRIDDEP_WAIT();   // norm's writes (g_h1q/g_h2q/g_R) must be visible

    // ---- Load 4 tiles (h1[I], h2[I], h1[J], h2[J]) into chunk-major SMEM
    {
        const uint4* base[4] = {
            (const uint4*)(g_h1q + (size_t)I * 128 * DDIM),
            (const uint4*)(g_h2q + (size_t)I * 128 * DDIM),
            (const uint4*)(g_h1q + (size_t)J * 128 * DDIM),
            (const uint4*)(g_h2q + (size_t)J * 128 * DDIM)
        };
        #pragma unroll
        for (int it = 0; it < 16; it++) {
            int tile = it >> 2;
            int lidx = tid + (it & 3) * 256;   // chunk index within tile (r*8+c)
            int r = lidx >> 3, c = lidx & 7;
            uint32_t off = (uint32_t)tile * SM_TILE
                         + (uint32_t)c * CH_STRIDE + (uint32_t)r * 16u;
            *(uint4*)(smem + off) = base[tile][lidx];
        }
    }
    __syncthreads();

    int wm = wid >> 2;          // 0..1  (M)
    int wn = wid & 3;           // 0..3  (N)
    int a_r  = wm * 64 + (lane & 15);
    int a_cp = lane >> 4;
    int b_r  = wn * 32 + ((lane >> 4) << 3) + (lane & 7);
    int b_cp = (lane >> 3) & 1;

    // Per-lane invariant parts of the LDSM addresses (chunk-major layout)
    uint32_t aLane = (uint32_t)a_cp * CH_STRIDE + (uint32_t)a_r * 16u;
    uint32_t bLane = (uint32_t)b_cp * CH_STRIDE + (uint32_t)b_r * 16u;

    #pragma unroll 1
    for (int g = 0; g < ngemm; g++) {
        uint32_t As = sb + ((g == 1 || g == 3) ? 1u : 0u) * SM_TILE;
        uint32_t Bs = sb + ((g == 1 || g == 2) ? 3u : 2u) * SM_TILE;

        float* Rrow; float* Rcol; bool docol;
        if (g == 0)      { Rrow = g_R + I*128;             Rcol = g_R + J*128;             docol = offd; }
        else if (g == 1) { Rrow = g_R + 3*NROWS + I*128;   Rcol = g_R + 3*NROWS + J*128;   docol = offd; }
        else if (g == 2) { Rrow = g_R + NROWS + I*128;     Rcol = g_R + 2*NROWS + J*128;   docol = true; }
        else             { Rrow = g_R + 2*NROWS + I*128;   Rcol = g_R + NROWS + J*128;     docol = true; }

        uint32_t aBase = As + aLane;
        uint32_t bBase = Bs + bLane;

        // ---- ks-outer mainloop: f16x2 accumulators for the whole warp tile
        uint32_t acc[4][4][2];   // [mtile][ntile][half-pair]
        #pragma unroll
        for (int mt = 0; mt < 4; mt++)
            #pragma unroll
            for (int nt = 0; nt < 4; nt++) { acc[mt][nt][0] = 0u; acc[mt][nt][1] = 0u; }

        #pragma unroll
        for (int ks = 0; ks < 4; ks++) {
            uint32_t kofs = (uint32_t)ks * (2u * CH_STRIDE);   // 2 chunks per kstep
            uint32_t a[4][4];
            #pragma unroll
            for (int mt = 0; mt < 4; mt++)
                ldsm_x4(a[mt][0], a[mt][1], a[mt][2], a[mt][3],
                        aBase + kofs + (uint32_t)(mt * 256));
            uint32_t b[4][2];
            #pragma unroll
            for (int np = 0; np < 2; np++)
                ldsm_x4(b[np*2][0], b[np*2][1], b[np*2+1][0], b[np*2+1][1],
                        bBase + kofs + (uint32_t)(np * 256));
            #pragma unroll
            for (int mt = 0; mt < 4; mt++)
                #pragma unroll
                for (int nt = 0; nt < 4; nt++)
                    mma_fp8_h(acc[mt][nt], a[mt], b[nt]);
        }

        // ---- Epilogue: e = 2^acc, packed half2 throughout
        __half2 cp[4];
        #pragma unroll
        for (int nt = 0; nt < 4; nt++) cp[nt] = __half2half2(__ushort_as_half(0));

        #pragma unroll
        for (int mt = 0; mt < 4; mt++) {
            __half2 rpA = __half2half2(__ushort_as_half(0));  // (row r: c0,c1)
            __half2 rpB = rpA;                                 // (row r+8: c2,c3)
            #pragma unroll
            for (int nt = 0; nt < 4; nt++) {
                __half2 e01 = h2exp2(*(__half2*)&acc[mt][nt][0]);
                __half2 e23 = h2exp2(*(__half2*)&acc[mt][nt][1]);
                rpA = __hadd2(rpA, e01);
                rpB = __hadd2(rpB, e23);
                cp[nt] = __hadd2(cp[nt], __hadd2(e01, e23));   // (e0+e2, e1+e3)
            }
            rpA = __hadd2(rpA, __shfl_xor_sync(0xffffffffu, rpA, 1));
            rpA = __hadd2(rpA, __shfl_xor_sync(0xffffffffu, rpA, 2));
            rpB = __hadd2(rpB, __shfl_xor_sync(0xffffffffu, rpB, 1));
            rpB = __hadd2(rpB, __shfl_xor_sync(0xffffffffu, rpB, 2));
            if ((lane & 3) == 0) {
                int r0 = wm * 64 + mt * 16 + (lane >> 2);
                atomicAdd(&Rrow[r0],     __low2float(rpA) + __high2float(rpA));
                atomicAdd(&Rrow[r0 + 8], __low2float(rpB) + __high2float(rpB));
            }
        }

        // ---- Column sums for this GEMM
        if (docol) {
            #pragma unroll
            for (int nt = 0; nt < 4; nt++) {
                __half2 v = cp[nt];
                v = __hadd2(v, __shfl_xor_sync(0xffffffffu, v, 4));
                v = __hadd2(v, __shfl_xor_sync(0xffffffffu, v, 8));
                v = __hadd2(v, __shfl_xor_sync(0xffffffffu, v, 16));
                if (lane < 4) {
                    int c0 = wn * 32 + lane * 2 + nt * 8;
                    atomicAdd(&Rcol[c0],     __low2float(v));
                    atomicAdd(&Rcol[c0 + 1], __high2float(v));
                }
            }
        }
    }

    GRIDDEP_LAUNCH();   // all atomics above are visible to the final kernel
}

// ---------------------------------------------------------------------------
// Final scalar: 32 blocks x 256 threads, one row per thread.
// ---------------------------------------------------------------------------
__global__ void final_kernel(float* out) {
    __shared__ float sm[256];
    int t = threadIdx.x;
    int i = blockIdx.x * 256 + t;
    const float E5 = 148.4131591f;   // exp(1/tau), tau = 0.2

    GRIDDEP_WAIT();   // mma atomics into g_R must be visible

    float n1 = g_R[i]             + g_R[NROWS + i]     - E5;
    float n2 = g_R[3 * NROWS + i] + g_R[2 * NROWS + i] - E5;
    float s  = 0.5f * (__logf(n1) + __logf(n2)) - 5.0f * g_diag[i];

    sm[t] = s;
    __syncthreads();
    #pragma unroll
    for (int o = 128; o > 0; o >>= 1) {
        if (t < o) sm[t] += sm[t + o];
        __syncthreads();
    }
    if (t == 0) atomicAdd(out, sm[0] * (1.0f / NROWS));
}

// ---------------------------------------------------------------------------
extern "C" void kernel_launch(void* const* d_in, const int* in_sizes, int n_in,
                              void* d_out, int out_size) {
    const float* h1 = (const float*)d_in[0];
    const float* h2 = (const float*)d_in[1];
    float* out = (float*)d_out;

    cudaFuncSetAttribute(mma_exp_kernel,
                         cudaFuncAttributeMaxDynamicSharedMemorySize, SM_TOTAL);

    norm_kernel<<<NROWS / 16, 256>>>(h1, h2, out);

    // mma + final launched with programmatic dependent launch: the dependent
    // kernel's CTAs rasterize and run their prologue under the predecessor's
    // tail; griddepcontrol.wait gates data consumption.
    cudaLaunchAttribute attrs[1];
    attrs[0].id = cudaLaunchAttributeProgrammaticStreamSerialization;
    attrs[0].val.programmaticStreamSerializationAllowed = 1;

    cudaLaunchConfig_t cfg = {};
    cfg.gridDim = dim3(NPAIR, 1, 1);
    cfg.blockDim = dim3(256, 1, 1);
    cfg.dynamicSmemBytes = SM_TOTAL;
    cfg.stream = 0;
    cfg.attrs = attrs;
    cfg.numAttrs = 1;
    cudaLaunchKernelEx(&cfg, mma_exp_kernel);

    cudaLaunchConfig_t cfg2 = {};
    cfg2.gridDim = dim3(NROWS / 256, 1, 1);
    cfg2.blockDim = dim3(256, 1, 1);
    cfg2.dynamicSmemBytes = 0;
    cfg2.stream = 0;
    cfg2.attrs = attrs;
    cfg2.numAttrs = 1;
    cudaLaunchKernelEx(&cfg2, final_kernel, out);
}